// round 1
// baseline (speedup 1.0000x reference)
#include <cuda_runtime.h>

// ---------------------------------------------------------------------------
// MoE HyperModel, fp32 baseline (round 0).
// Pipeline (all on default stream, graph-capturable, zero allocations):
//   k_base : base[e,b,h] = s@W1s[e] + b1[e]   (also expert 16 == gating g1, relu)
//   k_gate : weights = softmax(g1 @ Wg2 + bg2)
//   k_h    : h[e, m=(c*8+b), k] = relu(base[e,b,k] + W1c[e,c,k])
//   k_gemm_eo : per-expert 256x512x2048 SGEMM, scaled by weights[b,e] -> eo
//   k_z    : z = sum_e eo[e] + sum_e w[b,e]*b2[e]
//   k_gemm_out: z @ {WA,WB} + bias -> d_out (A then Bm)
// ---------------------------------------------------------------------------

namespace {
constexpr int kEMB = 1024;
constexpr int kCTX = 32;
constexpr int kNE  = 16;
constexpr int kH1  = 2048;
constexpr int kH2  = 512;
constexpr int kB   = 8;
constexpr int kM   = kCTX * kB;     // 256 rows of the (c,b) matrix
constexpr int kFO  = 16384;         // F_IN*R == R*F_OUT
constexpr int kW1R = kEMB + kCTX;   // 1056 rows per expert in W1
}

// Scratch (static device arrays -- allocation-free).
__device__ float g_g1[kB * kH1];                     // 64 KB
__device__ float g_w[kB * kNE];                      // gating weights
__device__ float g_base[kNE * kB * kH1];             // 1 MB
__device__ float g_h[(size_t)kNE * kM * kH1];        // 32 MB
__device__ float g_eo[(size_t)kNE * kM * kH2];       // 8 MB
__device__ float g_z[kM * kH2];                      // 0.5 MB

// ---------------------------------------------------------------------------
// k_base: grid (16 jtiles, 17 "experts"); expert 16 == gating layer 1 (Wg1).
// 128 threads, each owns one output column j, 8 accumulators (one per batch).
// ---------------------------------------------------------------------------
__global__ __launch_bounds__(128) void k_base(
    const float* __restrict__ s,
    const float* __restrict__ W1, const float* __restrict__ b1,
    const float* __restrict__ Wg1, const float* __restrict__ bg1)
{
    __shared__ float ssm[kB * kEMB];   // 32 KB
    const int tid = threadIdx.x;
    const int e = blockIdx.y;                       // 0..16
    const int j = blockIdx.x * 128 + tid;           // 0..2047

    for (int i = tid; i < kB * kEMB; i += 128) ssm[i] = s[i];
    __syncthreads();

    const float* __restrict__ W = (e < kNE) ? (W1 + (size_t)e * kW1R * kH1) : Wg1;

    float acc[kB];
#pragma unroll
    for (int b = 0; b < kB; b++) acc[b] = 0.f;

#pragma unroll 4
    for (int i = 0; i < kEMB; i++) {
        const float w = W[(size_t)i * kH1 + j];
#pragma unroll
        for (int b = 0; b < kB; b++) acc[b] += ssm[b * kEMB + i] * w;
    }

    if (e < kNE) {
        const float bias = b1[e * kH1 + j];
#pragma unroll
        for (int b = 0; b < kB; b++)
            g_base[((size_t)e * kB + b) * kH1 + j] = acc[b] + bias;
    } else {
        const float bias = bg1[j];
#pragma unroll
        for (int b = 0; b < kB; b++)
            g_g1[b * kH1 + j] = fmaxf(acc[b] + bias, 0.f);
    }
}

// ---------------------------------------------------------------------------
// k_gate: 1 block, 128 threads. thread t -> (b = t/16, expert x = t%16).
// logits + softmax over 16 lanes (shfl within width-16 groups).
// ---------------------------------------------------------------------------
__global__ __launch_bounds__(128) void k_gate(
    const float* __restrict__ Wg2, const float* __restrict__ bg2)
{
    const int t = threadIdx.x;
    const int b = t >> 4;
    const int x = t & 15;

    float acc = 0.f;
#pragma unroll 8
    for (int j = 0; j < kH1; j++)
        acc += g_g1[b * kH1 + j] * Wg2[j * kNE + x];
    acc += bg2[x];

    float mx = acc;
#pragma unroll
    for (int o = 8; o >= 1; o >>= 1)
        mx = fmaxf(mx, __shfl_xor_sync(0xffffffffu, mx, o, 16));
    const float ev = expf(acc - mx);
    float sm = ev;
#pragma unroll
    for (int o = 8; o >= 1; o >>= 1)
        sm += __shfl_xor_sync(0xffffffffu, sm, o, 16);

    g_w[b * kNE + x] = ev / sm;
}

// ---------------------------------------------------------------------------
// k_h: h[e][m][k] = relu(base[e][b][k] + W1c[e][c][k]), m = c*8+b.
// Fully vectorized float4; grid 8192 x 256.
// ---------------------------------------------------------------------------
__global__ __launch_bounds__(256) void k_h(const float* __restrict__ W1)
{
    const unsigned idx = blockIdx.x * 256u + threadIdx.x;  // float4 index, < 2,097,152
    const int k4 = idx & 511;          // H1/4 = 512
    const int m  = (idx >> 9) & 255;
    const int e  = idx >> 17;
    const int c  = m >> 3;
    const int b  = m & 7;

    const float4 bs = reinterpret_cast<const float4*>(g_base)[(e * kB + b) * (kH1 / 4) + k4];
    const float4 wc = reinterpret_cast<const float4*>(
        W1 + ((size_t)e * kW1R + kEMB + c) * kH1)[k4];

    float4 r;
    r.x = fmaxf(bs.x + wc.x, 0.f);
    r.y = fmaxf(bs.y + wc.y, 0.f);
    r.z = fmaxf(bs.z + wc.z, 0.f);
    r.w = fmaxf(bs.w + wc.w, 0.f);
    reinterpret_cast<float4*>(g_h)[idx] = r;
}

// ---------------------------------------------------------------------------
// k_gemm_eo: per-expert 256x512 = h[e](256x2048) @ W2[e](2048x512),
// scaled by weights[b,e] on store. Tile 128x64, K-tile 16, 256 threads,
// 8x4 microtile. Grid: (8 ntiles, 2 mtiles, 16 experts).
// ---------------------------------------------------------------------------
__global__ __launch_bounds__(256) void k_gemm_eo(const float* __restrict__ W2)
{
    __shared__ float As[16][128];   // k-major for vectorized m-loads
    __shared__ float Bs[16][64];

    const int e  = blockIdx.z;
    const int m0 = blockIdx.y * 128;
    const int n0 = blockIdx.x * 64;
    const int t  = threadIdx.x;
    const int tx = t & 15;          // n-slot (4 cols)
    const int ty = t >> 4;          // m-slot (8 rows)

    const float* __restrict__ A = g_h + (size_t)e * kM * kH1;
    const float* __restrict__ B = W2 + (size_t)e * kH1 * kH2;

    float acc[8][4];
#pragma unroll
    for (int i = 0; i < 8; i++)
#pragma unroll
        for (int j = 0; j < 4; j++) acc[i][j] = 0.f;

    const int r    = t >> 1;        // A-fill row, 0..127
    const int half = t & 1;         // A-fill k-half
    const int br   = t >> 4;        // B-fill row 0..15
    const int bc   = (t & 15) * 4;  // B-fill col

    for (int kt = 0; kt < kH1; kt += 16) {
        const float4* ag = reinterpret_cast<const float4*>(
            A + (size_t)(m0 + r) * kH1 + kt + half * 8);
        const float4 a0 = ag[0];
        const float4 a1 = ag[1];
        const float4 bv = *reinterpret_cast<const float4*>(
            B + (size_t)(kt + br) * kH2 + n0 + bc);

        __syncthreads();
        As[half * 8 + 0][r] = a0.x;  As[half * 8 + 1][r] = a0.y;
        As[half * 8 + 2][r] = a0.z;  As[half * 8 + 3][r] = a0.w;
        As[half * 8 + 4][r] = a1.x;  As[half * 8 + 5][r] = a1.y;
        As[half * 8 + 6][r] = a1.z;  As[half * 8 + 7][r] = a1.w;
        *reinterpret_cast<float4*>(&Bs[br][bc]) = bv;
        __syncthreads();

#pragma unroll
        for (int kk = 0; kk < 16; kk++) {
            const float4 a0r = *reinterpret_cast<const float4*>(&As[kk][ty * 8]);
            const float4 a1r = *reinterpret_cast<const float4*>(&As[kk][ty * 8 + 4]);
            const float4 b4  = *reinterpret_cast<const float4*>(&Bs[kk][tx * 4]);
            const float av[8] = {a0r.x, a0r.y, a0r.z, a0r.w, a1r.x, a1r.y, a1r.z, a1r.w};
            const float bw[4] = {b4.x, b4.y, b4.z, b4.w};
#pragma unroll
            for (int i = 0; i < 8; i++)
#pragma unroll
                for (int j = 0; j < 4; j++) acc[i][j] += av[i] * bw[j];
        }
    }

#pragma unroll
    for (int i = 0; i < 8; i++) {
        const int m = m0 + ty * 8 + i;
        const int b = m & 7;
        const float scale = g_w[b * kNE + e];
        float4 o;
        o.x = scale * acc[i][0]; o.y = scale * acc[i][1];
        o.z = scale * acc[i][2]; o.w = scale * acc[i][3];
        *reinterpret_cast<float4*>(
            &g_eo[((size_t)e * kM + m) * kH2 + n0 + tx * 4]) = o;
    }
}

// ---------------------------------------------------------------------------
// k_z: z[m][n] = sum_e eo[e][m][n] + sum_e w[b,e]*b2[e][n]. Grid 512 x 256.
// ---------------------------------------------------------------------------
__global__ __launch_bounds__(256) void k_z(const float* __restrict__ b2)
{
    const int idx = blockIdx.x * 256 + threadIdx.x;  // < 131072
    const int n = idx & (kH2 - 1);
    const int m = idx >> 9;
    const int b = m & 7;

    float acc = 0.f;
#pragma unroll
    for (int e = 0; e < kNE; e++)
        acc += g_eo[(size_t)e * (kM * kH2) + idx] + g_w[b * kNE + e] * b2[e * kH2 + n];
    g_z[idx] = acc;
}

// ---------------------------------------------------------------------------
// k_gemm_out: (256x512) @ (512x16384) + bias, twice (WA->A, WB->Bm).
// Same tile as k_gemm_eo, K=512. Grid: (256 ntiles, 2 mtiles, 2 matrices).
// ---------------------------------------------------------------------------
__global__ __launch_bounds__(256) void k_gemm_out(
    const float* __restrict__ WA, const float* __restrict__ bA,
    const float* __restrict__ WB, const float* __restrict__ bB,
    float* __restrict__ out)
{
    __shared__ float As[16][128];
    __shared__ float Bs[16][64];

    const int mat = blockIdx.z;
    const float* __restrict__ B    = mat ? WB : WA;
    const float* __restrict__ bias = mat ? bB : bA;
    float* __restrict__ o = out + (size_t)mat * kM * kFO;

    const int m0 = blockIdx.y * 128;
    const int n0 = blockIdx.x * 64;
    const int t  = threadIdx.x;
    const int tx = t & 15;
    const int ty = t >> 4;

    float acc[8][4];
#pragma unroll
    for (int i = 0; i < 8; i++)
#pragma unroll
        for (int j = 0; j < 4; j++) acc[i][j] = 0.f;

    const int r    = t >> 1;
    const int half = t & 1;
    const int br   = t >> 4;
    const int bc   = (t & 15) * 4;

    for (int kt = 0; kt < kH2; kt += 16) {
        const float4* ag = reinterpret_cast<const float4*>(
            g_z + (size_t)(m0 + r) * kH2 + kt + half * 8);
        const float4 a0 = ag[0];
        const float4 a1 = ag[1];
        const float4 bv = *reinterpret_cast<const float4*>(
            B + (size_t)(kt + br) * kFO + n0 + bc);

        __syncthreads();
        As[half * 8 + 0][r] = a0.x;  As[half * 8 + 1][r] = a0.y;
        As[half * 8 + 2][r] = a0.z;  As[half * 8 + 3][r] = a0.w;
        As[half * 8 + 4][r] = a1.x;  As[half * 8 + 5][r] = a1.y;
        As[half * 8 + 6][r] = a1.z;  As[half * 8 + 7][r] = a1.w;
        *reinterpret_cast<float4*>(&Bs[br][bc]) = bv;
        __syncthreads();

#pragma unroll
        for (int kk = 0; kk < 16; kk++) {
            const float4 a0r = *reinterpret_cast<const float4*>(&As[kk][ty * 8]);
            const float4 a1r = *reinterpret_cast<const float4*>(&As[kk][ty * 8 + 4]);
            const float4 b4  = *reinterpret_cast<const float4*>(&Bs[kk][tx * 4]);
            const float av[8] = {a0r.x, a0r.y, a0r.z, a0r.w, a1r.x, a1r.y, a1r.z, a1r.w};
            const float bw[4] = {b4.x, b4.y, b4.z, b4.w};
#pragma unroll
            for (int i = 0; i < 8; i++)
#pragma unroll
                for (int j = 0; j < 4; j++) acc[i][j] += av[i] * bw[j];
        }
    }

    const int n = n0 + tx * 4;
    const float4 bs4 = *reinterpret_cast<const float4*>(&bias[n]);
#pragma unroll
    for (int i = 0; i < 8; i++) {
        const int m = m0 + ty * 8 + i;
        float4 ov;
        ov.x = acc[i][0] + bs4.x; ov.y = acc[i][1] + bs4.y;
        ov.z = acc[i][2] + bs4.z; ov.w = acc[i][3] + bs4.w;
        *reinterpret_cast<float4*>(&o[(size_t)m * kFO + n]) = ov;
    }
}

// ---------------------------------------------------------------------------
// kernel_launch
// ---------------------------------------------------------------------------
extern "C" void kernel_launch(void* const* d_in, const int* in_sizes, int n_in,
                              void* d_out, int out_size)
{
    const float* s   = (const float*)d_in[0];
    const float* Wg1 = (const float*)d_in[1];
    const float* bg1 = (const float*)d_in[2];
    const float* Wg2 = (const float*)d_in[3];
    const float* bg2 = (const float*)d_in[4];
    const float* W1  = (const float*)d_in[5];
    const float* b1  = (const float*)d_in[6];
    const float* W2  = (const float*)d_in[7];
    const float* b2  = (const float*)d_in[8];
    const float* WA  = (const float*)d_in[9];
    const float* bA  = (const float*)d_in[10];
    const float* WB  = (const float*)d_in[11];
    const float* bB  = (const float*)d_in[12];
    float* out = (float*)d_out;

    k_base<<<dim3(kH1 / 128, kNE + 1), 128>>>(s, W1, b1, Wg1, bg1);
    k_gate<<<1, 128>>>(Wg2, bg2);
    k_h<<<(kNE * kM * kH1 / 4) / 256, 256>>>(W1);
    k_gemm_eo<<<dim3(kH2 / 64, kM / 128, kNE), 256>>>(W2);
    k_z<<<(kM * kH2) / 256, 256>>>(b2);
    k_gemm_out<<<dim3(kFO / 64, kM / 128, 2), 256>>>(WA, bA, WB, bB, out);
}

// round 2
// speedup vs baseline: 1.0938x; 1.0938x over previous
#include <cuda_runtime.h>
#include <mma.h>

using namespace nvcuda;

// ---------------------------------------------------------------------------
// MoE HyperModel, round 1: tf32 wmma tensor-core GEMMs.
//   k_base : base[e,b,h] = s@W1s[e] + b1[e]  (expert 16 == gating g1, relu)  fp32
//   k_gate : weights = softmax(g1 @ Wg2 + bg2)
//   k_h    : h[e,m,k] = tf32( w[b,e] * relu(base[e,b,k] + W1c[e,c,k]) )  (w folded in!)
//   k_gemm_eo : per-expert 256x512x2048 tf32 wmma GEMM -> eo
//   k_z    : z = tf32( sum_e eo[e] + sum_e w[b,e]*b2[e] )
//   k_gemm_out: z @ {WA,WB} + bias -> d_out, tf32 wmma
// ---------------------------------------------------------------------------

namespace {
constexpr int kEMB = 1024;
constexpr int kCTX = 32;
constexpr int kNE  = 16;
constexpr int kH1  = 2048;
constexpr int kH2  = 512;
constexpr int kB   = 8;
constexpr int kM   = kCTX * kB;     // 256
constexpr int kFO  = 16384;
constexpr int kW1R = kEMB + kCTX;   // 1056

constexpr int kLDA = 40;  // smem A row stride (floats), 32B-aligned rows
constexpr int kLDB = 72;  // smem B row stride (floats)
}

// Scratch (static device arrays -- allocation-free).
__device__ float g_g1[kB * kH1];
__device__ float g_w[kB * kNE];
__device__ float g_base[kNE * kB * kH1];
__device__ float g_h[(size_t)kNE * kM * kH1];        // 32 MB, tf32-rounded
__device__ float g_eo[(size_t)kNE * kM * kH2];       // 8 MB
__device__ float g_z[kM * kH2];                      // tf32-rounded

// ---------------------------------------------------------------------------
// k_base: fp32. grid (16 jtiles, 17 "experts"); expert 16 == gating layer 1.
// ---------------------------------------------------------------------------
__global__ __launch_bounds__(128) void k_base(
    const float* __restrict__ s,
    const float* __restrict__ W1, const float* __restrict__ b1,
    const float* __restrict__ Wg1, const float* __restrict__ bg1)
{
    __shared__ float ssm[kB * kEMB];
    const int tid = threadIdx.x;
    const int e = blockIdx.y;
    const int j = blockIdx.x * 128 + tid;

    for (int i = tid; i < kB * kEMB; i += 128) ssm[i] = s[i];
    __syncthreads();

    const float* __restrict__ W = (e < kNE) ? (W1 + (size_t)e * kW1R * kH1) : Wg1;

    float acc[kB];
#pragma unroll
    for (int b = 0; b < kB; b++) acc[b] = 0.f;

#pragma unroll 4
    for (int i = 0; i < kEMB; i++) {
        const float w = W[(size_t)i * kH1 + j];
#pragma unroll
        for (int b = 0; b < kB; b++) acc[b] += ssm[b * kEMB + i] * w;
    }

    if (e < kNE) {
        const float bias = b1[e * kH1 + j];
#pragma unroll
        for (int b = 0; b < kB; b++)
            g_base[((size_t)e * kB + b) * kH1 + j] = acc[b] + bias;
    } else {
        const float bias = bg1[j];
#pragma unroll
        for (int b = 0; b < kB; b++)
            g_g1[b * kH1 + j] = fmaxf(acc[b] + bias, 0.f);
    }
}

// ---------------------------------------------------------------------------
// k_gate: softmax over 16 experts per batch row.
// ---------------------------------------------------------------------------
__global__ __launch_bounds__(128) void k_gate(
    const float* __restrict__ Wg2, const float* __restrict__ bg2)
{
    const int t = threadIdx.x;
    const int b = t >> 4;
    const int x = t & 15;

    float acc = 0.f;
#pragma unroll 8
    for (int j = 0; j < kH1; j++)
        acc += g_g1[b * kH1 + j] * Wg2[j * kNE + x];
    acc += bg2[x];

    float mx = acc;
#pragma unroll
    for (int o = 8; o >= 1; o >>= 1)
        mx = fmaxf(mx, __shfl_xor_sync(0xffffffffu, mx, o, 16));
    const float ev = expf(acc - mx);
    float sm = ev;
#pragma unroll
    for (int o = 8; o >= 1; o >>= 1)
        sm += __shfl_xor_sync(0xffffffffu, sm, o, 16);

    g_w[b * kNE + x] = ev / sm;
}

// ---------------------------------------------------------------------------
// k_h: h = tf32( w[b,e] * relu(base + W1c) ). Weight fold + pre-round.
// ---------------------------------------------------------------------------
__global__ __launch_bounds__(256) void k_h(const float* __restrict__ W1)
{
    const unsigned idx = blockIdx.x * 256u + threadIdx.x;
    const int k4 = idx & 511;
    const int m  = (idx >> 9) & 255;
    const int e  = idx >> 17;
    const int c  = m >> 3;
    const int b  = m & 7;

    const float scale = g_w[b * kNE + e];
    const float4 bs = reinterpret_cast<const float4*>(g_base)[(e * kB + b) * (kH1 / 4) + k4];
    const float4 wc = reinterpret_cast<const float4*>(
        W1 + ((size_t)e * kW1R + kEMB + c) * kH1)[k4];

    float4 r;
    r.x = wmma::__float_to_tf32(scale * fmaxf(bs.x + wc.x, 0.f));
    r.y = wmma::__float_to_tf32(scale * fmaxf(bs.y + wc.y, 0.f));
    r.z = wmma::__float_to_tf32(scale * fmaxf(bs.z + wc.z, 0.f));
    r.w = wmma::__float_to_tf32(scale * fmaxf(bs.w + wc.w, 0.f));
    reinterpret_cast<float4*>(g_h)[idx] = r;
}

// ---------------------------------------------------------------------------
// k_gemm_eo: per-expert 256x512x2048 tf32 GEMM. Block tile 128x64, K-tile 32,
// 8 warps (4m x 2n), warp tile 32x32 via wmma 16x16x8.
// Grid: (8 ntiles, 2 mtiles, 16 experts).
// ---------------------------------------------------------------------------
__global__ __launch_bounds__(256) void k_gemm_eo(const float* __restrict__ W2)
{
    __shared__ __align__(16) float As[128 * kLDA];   // 20 KB
    __shared__ __align__(16) float Bs[32 * kLDB];    // 9 KB

    const int e  = blockIdx.z;
    const int m0 = blockIdx.y * 128;
    const int n0 = blockIdx.x * 64;
    const int t  = threadIdx.x;
    const int warp = t >> 5;
    const int wm = warp >> 1;     // 0..3
    const int wn = warp & 1;      // 0..1

    const float* __restrict__ A = g_h + (size_t)e * kM * kH1;
    const float* __restrict__ B = W2 + (size_t)e * kH1 * kH2;

    wmma::fragment<wmma::accumulator, 16, 16, 8, float> acc[2][2];
#pragma unroll
    for (int i = 0; i < 2; i++)
#pragma unroll
        for (int j = 0; j < 2; j++) wmma::fill_fragment(acc[i][j], 0.f);

    const int ar = t >> 1, ak = (t & 1) * 16;   // A fill: 1 row, 16 k's
    const int br = t >> 3, bn = (t & 7) * 8;    // B fill: 1 row, 8 n's

    for (int kt = 0; kt < kH1; kt += 32) {
        float4 av[4];
#pragma unroll
        for (int i = 0; i < 4; i++)
            av[i] = *reinterpret_cast<const float4*>(
                A + (size_t)(m0 + ar) * kH1 + kt + ak + 4 * i);
        float bv[8];
#pragma unroll
        for (int i = 0; i < 8; i++)
            bv[i] = wmma::__float_to_tf32(B[(size_t)(kt + br) * kH2 + n0 + bn + i]);

        __syncthreads();
#pragma unroll
        for (int i = 0; i < 4; i++)
            *reinterpret_cast<float4*>(&As[ar * kLDA + ak + 4 * i]) = av[i];
#pragma unroll
        for (int i = 0; i < 8; i++) Bs[br * kLDB + bn + i] = bv[i];
        __syncthreads();

#pragma unroll
        for (int kk = 0; kk < 4; kk++) {
            wmma::fragment<wmma::matrix_a, 16, 16, 8, wmma::precision::tf32, wmma::row_major> af[2];
            wmma::fragment<wmma::matrix_b, 16, 16, 8, wmma::precision::tf32, wmma::row_major> bf[2];
            wmma::load_matrix_sync(af[0], &As[(wm * 32) * kLDA + kk * 8], kLDA);
            wmma::load_matrix_sync(af[1], &As[(wm * 32 + 16) * kLDA + kk * 8], kLDA);
            wmma::load_matrix_sync(bf[0], &Bs[(kk * 8) * kLDB + wn * 32], kLDB);
            wmma::load_matrix_sync(bf[1], &Bs[(kk * 8) * kLDB + wn * 32 + 16], kLDB);
#pragma unroll
            for (int i = 0; i < 2; i++)
#pragma unroll
                for (int j = 0; j < 2; j++)
                    wmma::mma_sync(acc[i][j], af[i], bf[j], acc[i][j]);
        }
    }

#pragma unroll
    for (int i = 0; i < 2; i++)
#pragma unroll
        for (int j = 0; j < 2; j++)
            wmma::store_matrix_sync(
                &g_eo[((size_t)e * kM + m0 + wm * 32 + i * 16) * kH2 + n0 + wn * 32 + j * 16],
                acc[i][j], kH2, wmma::mem_row_major);
}

// ---------------------------------------------------------------------------
// k_z: z = tf32( sum_e eo + sum_e w[b,e]*b2[e] ).
// ---------------------------------------------------------------------------
__global__ __launch_bounds__(256) void k_z(const float* __restrict__ b2)
{
    const int idx = blockIdx.x * 256 + threadIdx.x;
    const int n = idx & (kH2 - 1);
    const int m = idx >> 9;
    const int b = m & 7;

    float acc = 0.f;
#pragma unroll
    for (int e = 0; e < kNE; e++)
        acc += g_eo[(size_t)e * (kM * kH2) + idx] + g_w[b * kNE + e] * b2[e * kH2 + n];
    g_z[idx] = wmma::__float_to_tf32(acc);
}

// ---------------------------------------------------------------------------
// k_gemm_out: (256x512)@(512x16384)+bias, twice. Same wmma tiling, K=512.
// Smem reused as epilogue stage (union). Grid (256 ntiles, 2 mtiles, 2 mats).
// ---------------------------------------------------------------------------
__global__ __launch_bounds__(256) void k_gemm_out(
    const float* __restrict__ WA, const float* __restrict__ bA,
    const float* __restrict__ WB, const float* __restrict__ bB,
    float* __restrict__ out)
{
    __shared__ __align__(16) float smem[128 * 64];   // 32 KB: load bufs, then stage
    float* As = smem;                 // 128*40 = 5120
    float* Bs = smem + 128 * kLDA;    // 32*72  = 2304 (total 7424 <= 8192)

    const int mat = blockIdx.z;
    const float* __restrict__ B    = mat ? WB : WA;
    const float* __restrict__ bias = mat ? bB : bA;
    float* __restrict__ o = out + (size_t)mat * kM * kFO;

    const int m0 = blockIdx.y * 128;
    const int n0 = blockIdx.x * 64;
    const int t  = threadIdx.x;
    const int warp = t >> 5;
    const int wm = warp >> 1;
    const int wn = warp & 1;

    wmma::fragment<wmma::accumulator, 16, 16, 8, float> acc[2][2];
#pragma unroll
    for (int i = 0; i < 2; i++)
#pragma unroll
        for (int j = 0; j < 2; j++) wmma::fill_fragment(acc[i][j], 0.f);

    const int ar = t >> 1, ak = (t & 1) * 16;
    const int br = t >> 3, bn = (t & 7) * 8;

    for (int kt = 0; kt < kH2; kt += 32) {
        float4 av[4];
#pragma unroll
        for (int i = 0; i < 4; i++)
            av[i] = *reinterpret_cast<const float4*>(
                g_z + (size_t)(m0 + ar) * kH2 + kt + ak + 4 * i);
        float bv[8];
#pragma unroll
        for (int i = 0; i < 8; i++)
            bv[i] = wmma::__float_to_tf32(B[(size_t)(kt + br) * kFO + n0 + bn + i]);

        __syncthreads();
#pragma unroll
        for (int i = 0; i < 4; i++)
            *reinterpret_cast<float4*>(&As[ar * kLDA + ak + 4 * i]) = av[i];
#pragma unroll
        for (int i = 0; i < 8; i++) Bs[br * kLDB + bn + i] = bv[i];
        __syncthreads();

#pragma unroll
        for (int kk = 0; kk < 4; kk++) {
            wmma::fragment<wmma::matrix_a, 16, 16, 8, wmma::precision::tf32, wmma::row_major> af[2];
            wmma::fragment<wmma::matrix_b, 16, 16, 8, wmma::precision::tf32, wmma::row_major> bf[2];
            wmma::load_matrix_sync(af[0], &As[(wm * 32) * kLDA + kk * 8], kLDA);
            wmma::load_matrix_sync(af[1], &As[(wm * 32 + 16) * kLDA + kk * 8], kLDA);
            wmma::load_matrix_sync(bf[0], &Bs[(kk * 8) * kLDB + wn * 32], kLDB);
            wmma::load_matrix_sync(bf[1], &Bs[(kk * 8) * kLDB + wn * 32 + 16], kLDB);
#pragma unroll
            for (int i = 0; i < 2; i++)
#pragma unroll
                for (int j = 0; j < 2; j++)
                    wmma::mma_sync(acc[i][j], af[i], bf[j], acc[i][j]);
        }
    }

    // Epilogue: stage accumulators in smem (load buffers are dead), add bias,
    // vectorized global store.
    __syncthreads();
#pragma unroll
    for (int i = 0; i < 2; i++)
#pragma unroll
        for (int j = 0; j < 2; j++)
            wmma::store_matrix_sync(&smem[(wm * 32 + i * 16) * 64 + wn * 32 + j * 16],
                                    acc[i][j], 64, wmma::mem_row_major);
    __syncthreads();

    const int r  = t >> 1;
    const int cb = (t & 1) * 32;
#pragma unroll
    for (int i = 0; i < 8; i++) {
        float4 v  = *reinterpret_cast<const float4*>(&smem[r * 64 + cb + 4 * i]);
        float4 bv = *reinterpret_cast<const float4*>(&bias[n0 + cb + 4 * i]);
        v.x += bv.x; v.y += bv.y; v.z += bv.z; v.w += bv.w;
        *reinterpret_cast<float4*>(&o[(size_t)(m0 + r) * kFO + n0 + cb + 4 * i]) = v;
    }
}

// ---------------------------------------------------------------------------
// kernel_launch
// ---------------------------------------------------------------------------
extern "C" void kernel_launch(void* const* d_in, const int* in_sizes, int n_in,
                              void* d_out, int out_size)
{
    const float* s   = (const float*)d_in[0];
    const float* Wg1 = (const float*)d_in[1];
    const float* bg1 = (const float*)d_in[2];
    const float* Wg2 = (const float*)d_in[3];
    const float* bg2 = (const float*)d_in[4];
    const float* W1  = (const float*)d_in[5];
    const float* b1  = (const float*)d_in[6];
    const float* W2  = (const float*)d_in[7];
    const float* b2  = (const float*)d_in[8];
    const float* WA  = (const float*)d_in[9];
    const float* bA  = (const float*)d_in[10];
    const float* WB  = (const float*)d_in[11];
    const float* bB  = (const float*)d_in[12];
    float* out = (float*)d_out;

    k_base<<<dim3(kH1 / 128, kNE + 1), 128>>>(s, W1, b1, Wg1, bg1);
    k_gate<<<1, 128>>>(Wg2, bg2);
    k_h<<<(kNE * kM * kH1 / 4) / 256, 256>>>(W1);
    k_gemm_eo<<<dim3(kH2 / 64, kM / 128, kNE), 256>>>(W2);
    k_z<<<(kM * kH2) / 256, 256>>>(b2);
    k_gemm_out<<<dim3(kFO / 64, kM / 128, 2), 256>>>(WA, bA, WB, bB, out);
}

// round 4
// speedup vs baseline: 1.7255x; 1.5775x over previous
#include <cuda_runtime.h>
#include <cstdint>
#include <mma.h>

using namespace nvcuda;

// ---------------------------------------------------------------------------
// MoE HyperModel, round 3 (= round-2 design + cstdint fix):
// cp.async double-buffered tf32 wmma GEMMs, split-K eo GEMM,
// parallelized k_base / k_gate.
// ---------------------------------------------------------------------------

namespace {
constexpr int kEMB = 1024;
constexpr int kCTX = 32;
constexpr int kNE  = 16;
constexpr int kH1  = 2048;
constexpr int kH2  = 512;
constexpr int kB   = 8;
constexpr int kM   = kCTX * kB;     // 256
constexpr int kFO  = 16384;
constexpr int kW1R = kEMB + kCTX;   // 1056

constexpr int kLDAs = 36;   // smem A tile stride (floats)
constexpr int kLDBs = 132;  // smem B tile stride (floats)
constexpr int kAbuf = 128 * kLDAs;  // 4608 floats
constexpr int kBbuf = 32 * kLDBs;   // 4224 floats
constexpr int kSmemGemm = (2 * kAbuf + 2 * kBbuf) * 4;  // 70656 bytes
}

// Scratch (static device arrays -- allocation-free).
__device__ float g_g1[kB * kH1];
__device__ float g_w[kB * kNE];
__device__ float g_base[kNE * kB * kH1];
__device__ float g_h[(size_t)kNE * kM * kH1];            // 32 MB, tf32-rounded
__device__ float g_eo2[(size_t)2 * kNE * kM * kH2];      // 16 MB (split-K partials)
__device__ float g_z[kM * kH2];                          // tf32-rounded

// --------------------------- cp.async helpers ------------------------------
__device__ __forceinline__ void cp_async16(float* smem_dst, const float* gmem_src) {
    unsigned int s = (unsigned int)__cvta_generic_to_shared(smem_dst);
    asm volatile("cp.async.cg.shared.global [%0], [%1], 16;\n" :: "r"(s), "l"(gmem_src));
}
__device__ __forceinline__ void cp_commit() {
    asm volatile("cp.async.commit_group;\n");
}
template <int N>
__device__ __forceinline__ void cp_wait() {
    asm volatile("cp.async.wait_group %0;\n" :: "n"(N));
}

// Load one 128x32 A tile + 32x128 B tile into smem (raw fp32 bits; tf32
// truncation happens inside the HMMA).
template <int LDA_G, int LDB_G>
__device__ __forceinline__ void load_tiles(float* As, float* Bs,
                                           const float* A, const float* B,
                                           int kt, int t)
{
#pragma unroll
    for (int i = 0; i < 4; i++) {
        const int c = t + i * 256;
        const int row = c >> 3, c4 = c & 7;
        cp_async16(As + row * kLDAs + c4 * 4, A + (size_t)row * LDA_G + kt + c4 * 4);
    }
#pragma unroll
    for (int i = 0; i < 4; i++) {
        const int c = t + i * 256;
        const int row = c >> 5, c4 = c & 31;
        cp_async16(Bs + row * kLDBs + c4 * 4, B + (size_t)(kt + row) * LDB_G + c4 * 4);
    }
}

// Warp-tile (64x32) compute over one 32-K smem tile.
__device__ __forceinline__ void gemm_tile_compute(
    const float* As, const float* Bs, int wm, int wn,
    wmma::fragment<wmma::accumulator, 16, 16, 8, float> (&acc)[4][2])
{
#pragma unroll
    for (int kk = 0; kk < 4; kk++) {
        wmma::fragment<wmma::matrix_a, 16, 16, 8, wmma::precision::tf32, wmma::row_major> af[4];
        wmma::fragment<wmma::matrix_b, 16, 16, 8, wmma::precision::tf32, wmma::row_major> bf[2];
#pragma unroll
        for (int i = 0; i < 4; i++)
            wmma::load_matrix_sync(af[i], As + (wm * 64 + i * 16) * kLDAs + kk * 8, kLDAs);
#pragma unroll
        for (int j = 0; j < 2; j++)
            wmma::load_matrix_sync(bf[j], Bs + (kk * 8) * kLDBs + wn * 32 + j * 16, kLDBs);
#pragma unroll
        for (int i = 0; i < 4; i++)
#pragma unroll
            for (int j = 0; j < 2; j++)
                wmma::mma_sync(acc[i][j], af[i], bf[j], acc[i][j]);
    }
}

// ---------------------------------------------------------------------------
// k_base: base[e,b,:] = s @ W1s[e] + b1[e]; e==16 -> gating g1 (relu).
// 256 threads: two K-halves of 512 reduced through smem.
// ---------------------------------------------------------------------------
__global__ __launch_bounds__(256) void k_base(
    const float* __restrict__ s,
    const float* __restrict__ W1, const float* __restrict__ b1,
    const float* __restrict__ Wg1, const float* __restrict__ bg1)
{
    __shared__ float ssm[kB * kEMB];   // 32 KB
    __shared__ float red[128][kB];     // 4 KB
    const int t = threadIdx.x;
    const int e = blockIdx.y;
    const int jl = t & 127;
    const int half = t >> 7;
    const int j = blockIdx.x * 128 + jl;

    for (int i = t; i < kB * kEMB; i += 256) ssm[i] = s[i];
    __syncthreads();

    const float* __restrict__ W = (e < kNE) ? (W1 + (size_t)e * kW1R * kH1) : Wg1;

    float acc[kB];
#pragma unroll
    for (int b = 0; b < kB; b++) acc[b] = 0.f;

    const int i0 = half * 512;
#pragma unroll 4
    for (int i = i0; i < i0 + 512; i++) {
        const float w = W[(size_t)i * kH1 + j];
#pragma unroll
        for (int b = 0; b < kB; b++) acc[b] += ssm[b * kEMB + i] * w;
    }

    if (half) {
#pragma unroll
        for (int b = 0; b < kB; b++) red[jl][b] = acc[b];
    }
    __syncthreads();
    if (!half) {
#pragma unroll
        for (int b = 0; b < kB; b++) acc[b] += red[jl][b];
        if (e < kNE) {
            const float bias = b1[e * kH1 + j];
#pragma unroll
            for (int b = 0; b < kB; b++)
                g_base[((size_t)e * kB + b) * kH1 + j] = acc[b] + bias;
        } else {
            const float bias = bg1[j];
#pragma unroll
            for (int b = 0; b < kB; b++)
                g_g1[b * kH1 + j] = fmaxf(acc[b] + bias, 0.f);
        }
    }
}

// ---------------------------------------------------------------------------
// k_gate: 1024 threads; (b, kc, x) split-K over 8 chunks, smem reduce,
// then softmax by first 128 threads (shfl within width-16 groups).
// ---------------------------------------------------------------------------
__global__ __launch_bounds__(1024) void k_gate(
    const float* __restrict__ Wg2, const float* __restrict__ bg2)
{
    __shared__ float red[1024];
    const int t = threadIdx.x;
    const int b = t >> 7;
    const int rem = t & 127;
    const int kc = rem >> 4;
    const int x = rem & 15;

    float acc = 0.f;
    const int j0 = kc * 256;
#pragma unroll 4
    for (int j = j0; j < j0 + 256; j++)
        acc += g_g1[b * kH1 + j] * Wg2[j * kNE + x];
    red[t] = acc;
    __syncthreads();

    if (t < 128) {
        const int bb = t >> 4;
        const int xx = t & 15;
        float a = bg2[xx];
#pragma unroll
        for (int k = 0; k < 8; k++) a += red[bb * 128 + k * 16 + xx];

        float mx = a;
#pragma unroll
        for (int o = 8; o >= 1; o >>= 1)
            mx = fmaxf(mx, __shfl_xor_sync(0xffffffffu, mx, o, 16));
        const float ev = expf(a - mx);
        float sm = ev;
#pragma unroll
        for (int o = 8; o >= 1; o >>= 1)
            sm += __shfl_xor_sync(0xffffffffu, sm, o, 16);

        g_w[bb * kNE + xx] = ev / sm;
    }
}

// ---------------------------------------------------------------------------
// k_h: h = tf32( w[b,e] * relu(base + W1c) ). Weight fold + RNA pre-round.
// ---------------------------------------------------------------------------
__global__ __launch_bounds__(256) void k_h(const float* __restrict__ W1)
{
    const unsigned idx = blockIdx.x * 256u + threadIdx.x;
    const int k4 = idx & 511;
    const int m  = (idx >> 9) & 255;
    const int e  = idx >> 17;
    const int c  = m >> 3;
    const int b  = m & 7;

    const float scale = g_w[b * kNE + e];
    const float4 bs = reinterpret_cast<const float4*>(g_base)[(e * kB + b) * (kH1 / 4) + k4];
    const float4 wc = reinterpret_cast<const float4*>(
        W1 + ((size_t)e * kW1R + kEMB + c) * kH1)[k4];

    float4 r;
    r.x = wmma::__float_to_tf32(scale * fmaxf(bs.x + wc.x, 0.f));
    r.y = wmma::__float_to_tf32(scale * fmaxf(bs.y + wc.y, 0.f));
    r.z = wmma::__float_to_tf32(scale * fmaxf(bs.z + wc.z, 0.f));
    r.w = wmma::__float_to_tf32(scale * fmaxf(bs.w + wc.w, 0.f));
    reinterpret_cast<float4*>(g_h)[idx] = r;
}

// ---------------------------------------------------------------------------
// k_gemm_eo: split-K per-expert GEMM. Block tile 128x128, K-tile 32, cp.async
// double buffer, 8 warps (2m x 4n), warp tile 64x32.
// Grid: (4 ntiles, 2 mtiles, 32 = expert*2 + khalf).
// ---------------------------------------------------------------------------
__global__ __launch_bounds__(256) void k_gemm_eo(const float* __restrict__ W2)
{
    extern __shared__ float smem[];
    float* As = smem;                  // 2 * kAbuf
    float* Bs = smem + 2 * kAbuf;      // 2 * kBbuf

    const int zz = blockIdx.z;
    const int e  = zz >> 1;
    const int kh = zz & 1;
    const int m0 = blockIdx.y * 128;
    const int n0 = blockIdx.x * 128;
    const int t  = threadIdx.x;
    const int warp = t >> 5;
    const int wm = warp >> 2;
    const int wn = warp & 3;

    const float* A = g_h + (size_t)e * kM * kH1 + (size_t)m0 * kH1 + kh * 1024;
    const float* B = W2 + (size_t)e * kH1 * kH2 + (size_t)(kh * 1024) * kH2 + n0;

    wmma::fragment<wmma::accumulator, 16, 16, 8, float> acc[4][2];
#pragma unroll
    for (int i = 0; i < 4; i++)
#pragma unroll
        for (int j = 0; j < 2; j++) wmma::fill_fragment(acc[i][j], 0.f);

    constexpr int NT = 1024 / 32;
    load_tiles<kH1, kH2>(As, Bs, A, B, 0, t);
    cp_commit();

    for (int it = 0; it < NT; it++) {
        if (it + 1 < NT) {
            load_tiles<kH1, kH2>(As + ((it + 1) & 1) * kAbuf, Bs + ((it + 1) & 1) * kBbuf,
                                 A, B, (it + 1) * 32, t);
            cp_commit();
            cp_wait<1>();
        } else {
            cp_wait<0>();
        }
        __syncthreads();
        gemm_tile_compute(As + (it & 1) * kAbuf, Bs + (it & 1) * kBbuf, wm, wn, acc);
        __syncthreads();
    }

    float* O = g_eo2 + (size_t)zz * kM * kH2 + (size_t)m0 * kH2 + n0;
#pragma unroll
    for (int i = 0; i < 4; i++)
#pragma unroll
        for (int j = 0; j < 2; j++)
            wmma::store_matrix_sync(O + (size_t)(wm * 64 + i * 16) * kH2 + wn * 32 + j * 16,
                                    acc[i][j], kH2, wmma::mem_row_major);
}

// ---------------------------------------------------------------------------
// k_z: z = tf32( sum over 32 partial slabs + sum_e w[b,e]*b2[e] ).
// ---------------------------------------------------------------------------
__global__ __launch_bounds__(256) void k_z(const float* __restrict__ b2)
{
    const int idx = blockIdx.x * 256 + threadIdx.x;
    const int n = idx & (kH2 - 1);
    const int m = idx >> 9;
    const int b = m & 7;

    float acc = 0.f;
#pragma unroll
    for (int p = 0; p < 2 * kNE; p++)
        acc += g_eo2[(size_t)p * (kM * kH2) + idx];
#pragma unroll
    for (int e = 0; e < kNE; e++)
        acc += g_w[b * kNE + e] * b2[e * kH2 + n];
    g_z[idx] = wmma::__float_to_tf32(acc);
}

// ---------------------------------------------------------------------------
// k_gemm_out: (256x512)@(512x16384)+bias, twice. Same pipeline, K=512.
// Epilogue stages into the (dead) load buffers. Grid (128, 2, 2).
// ---------------------------------------------------------------------------
__global__ __launch_bounds__(256) void k_gemm_out(
    const float* __restrict__ WA, const float* __restrict__ bA,
    const float* __restrict__ WB, const float* __restrict__ bB,
    float* __restrict__ out)
{
    extern __shared__ float smem[];
    float* As = smem;
    float* Bs = smem + 2 * kAbuf;

    const int mat = blockIdx.z;
    const float* __restrict__ Bw   = (mat ? WB : WA);
    const float* __restrict__ bias = mat ? bB : bA;
    float* __restrict__ o = out + (size_t)mat * kM * kFO;

    const int m0 = blockIdx.y * 128;
    const int n0 = blockIdx.x * 128;
    const int t  = threadIdx.x;
    const int warp = t >> 5;
    const int wm = warp >> 2;
    const int wn = warp & 3;

    const float* A = g_z + (size_t)m0 * kH2;
    const float* B = Bw + n0;

    wmma::fragment<wmma::accumulator, 16, 16, 8, float> acc[4][2];
#pragma unroll
    for (int i = 0; i < 4; i++)
#pragma unroll
        for (int j = 0; j < 2; j++) wmma::fill_fragment(acc[i][j], 0.f);

    constexpr int NT = kH2 / 32;   // 16
    load_tiles<kH2, kFO>(As, Bs, A, B, 0, t);
    cp_commit();

    for (int it = 0; it < NT; it++) {
        if (it + 1 < NT) {
            load_tiles<kH2, kFO>(As + ((it + 1) & 1) * kAbuf, Bs + ((it + 1) & 1) * kBbuf,
                                 A, B, (it + 1) * 32, t);
            cp_commit();
            cp_wait<1>();
        } else {
            cp_wait<0>();
        }
        __syncthreads();
        gemm_tile_compute(As + (it & 1) * kAbuf, Bs + (it & 1) * kBbuf, wm, wn, acc);
        __syncthreads();
    }

    // Epilogue: stage 128x128 tile (stride 132) in dead load buffers.
    __syncthreads();
    float* stage = smem;   // 128*132 = 16896 floats <= 17664 available
#pragma unroll
    for (int i = 0; i < 4; i++)
#pragma unroll
        for (int j = 0; j < 2; j++)
            wmma::store_matrix_sync(stage + (wm * 64 + i * 16) * kLDBs + wn * 32 + j * 16,
                                    acc[i][j], kLDBs, wmma::mem_row_major);
    __syncthreads();

#pragma unroll
    for (int i = 0; i < 16; i++) {
        const int c = t + i * 256;           // float4 chunk in 128x128
        const int row = c >> 5, c4 = c & 31;
        float4 v  = *reinterpret_cast<const float4*>(stage + row * kLDBs + c4 * 4);
        float4 bv = *reinterpret_cast<const float4*>(bias + n0 + c4 * 4);
        v.x += bv.x; v.y += bv.y; v.z += bv.z; v.w += bv.w;
        *reinterpret_cast<float4*>(&o[(size_t)(m0 + row) * kFO + n0 + c4 * 4]) = v;
    }
}

// ---------------------------------------------------------------------------
// kernel_launch
// ---------------------------------------------------------------------------
extern "C" void kernel_launch(void* const* d_in, const int* in_sizes, int n_in,
                              void* d_out, int out_size)
{
    const float* s   = (const float*)d_in[0];
    const float* Wg1 = (const float*)d_in[1];
    const float* bg1 = (const float*)d_in[2];
    const float* Wg2 = (const float*)d_in[3];
    const float* bg2 = (const float*)d_in[4];
    const float* W1  = (const float*)d_in[5];
    const float* b1  = (const float*)d_in[6];
    const float* W2  = (const float*)d_in[7];
    const float* b2  = (const float*)d_in[8];
    const float* WA  = (const float*)d_in[9];
    const float* bA  = (const float*)d_in[10];
    const float* WB  = (const float*)d_in[11];
    const float* bB  = (const float*)d_in[12];
    float* out = (float*)d_out;

    cudaFuncSetAttribute(k_gemm_eo,  cudaFuncAttributeMaxDynamicSharedMemorySize, kSmemGemm);
    cudaFuncSetAttribute(k_gemm_out, cudaFuncAttributeMaxDynamicSharedMemorySize, kSmemGemm);

    k_base<<<dim3(kH1 / 128, kNE + 1), 256>>>(s, W1, b1, Wg1, bg1);
    k_gate<<<1, 1024>>>(Wg2, bg2);
    k_h<<<(kNE * kM * kH1 / 4) / 256, 256>>>(W1);
    k_gemm_eo<<<dim3(kH2 / 128, kM / 128, 2 * kNE), 256, kSmemGemm>>>(W2);
    k_z<<<(kM * kH2) / 256, 256>>>(b2);
    k_gemm_out<<<dim3(kFO / 128, kM / 128, 2), 256, kSmemGemm>>>(WA, bA, WB, bB, out);
}

// round 5
// speedup vs baseline: 1.7862x; 1.0352x over previous
#include <cuda_runtime.h>
#include <cstdint>
#include <mma.h>

using namespace nvcuda;

// ---------------------------------------------------------------------------
// MoE HyperModel, round 4: R3 + 2-CTA/SM occupancy on the GEMMs
// (__launch_bounds__(256,2)) + RNA rounding of B fragments (accuracy margin).
// ---------------------------------------------------------------------------

namespace {
constexpr int kEMB = 1024;
constexpr int kCTX = 32;
constexpr int kNE  = 16;
constexpr int kH1  = 2048;
constexpr int kH2  = 512;
constexpr int kB   = 8;
constexpr int kM   = kCTX * kB;     // 256
constexpr int kFO  = 16384;
constexpr int kW1R = kEMB + kCTX;   // 1056

constexpr int kLDAs = 36;   // smem A tile stride (floats)
constexpr int kLDBs = 132;  // smem B tile stride (floats)
constexpr int kAbuf = 128 * kLDAs;  // 4608 floats
constexpr int kBbuf = 32 * kLDBs;   // 4224 floats
constexpr int kSmemGemm = (2 * kAbuf + 2 * kBbuf) * 4;  // 70656 bytes
}

// Scratch (static device arrays -- allocation-free).
__device__ float g_g1[kB * kH1];
__device__ float g_w[kB * kNE];
__device__ float g_base[kNE * kB * kH1];
__device__ float g_h[(size_t)kNE * kM * kH1];            // 32 MB, tf32-rounded
__device__ float g_eo2[(size_t)2 * kNE * kM * kH2];      // 16 MB (split-K partials)
__device__ float g_z[kM * kH2];                          // tf32-rounded

// --------------------------- cp.async helpers ------------------------------
__device__ __forceinline__ void cp_async16(float* smem_dst, const float* gmem_src) {
    unsigned int s = (unsigned int)__cvta_generic_to_shared(smem_dst);
    asm volatile("cp.async.cg.shared.global [%0], [%1], 16;\n" :: "r"(s), "l"(gmem_src));
}
__device__ __forceinline__ void cp_commit() {
    asm volatile("cp.async.commit_group;\n");
}
template <int N>
__device__ __forceinline__ void cp_wait() {
    asm volatile("cp.async.wait_group %0;\n" :: "n"(N));
}

// Load one 128x32 A tile + 32x128 B tile into smem.
template <int LDA_G, int LDB_G>
__device__ __forceinline__ void load_tiles(float* As, float* Bs,
                                           const float* A, const float* B,
                                           int kt, int t)
{
#pragma unroll
    for (int i = 0; i < 4; i++) {
        const int c = t + i * 256;
        const int row = c >> 3, c4 = c & 7;
        cp_async16(As + row * kLDAs + c4 * 4, A + (size_t)row * LDA_G + kt + c4 * 4);
    }
#pragma unroll
    for (int i = 0; i < 4; i++) {
        const int c = t + i * 256;
        const int row = c >> 5, c4 = c & 31;
        cp_async16(Bs + row * kLDBs + c4 * 4, B + (size_t)(kt + row) * LDB_G + c4 * 4);
    }
}

// Warp-tile (64x32) compute over one 32-K smem tile. B fragments are
// RNA-rounded to tf32 in-register (B arrives as raw fp32 bits).
__device__ __forceinline__ void gemm_tile_compute(
    const float* As, const float* Bs, int wm, int wn,
    wmma::fragment<wmma::accumulator, 16, 16, 8, float> (&acc)[4][2])
{
#pragma unroll
    for (int kk = 0; kk < 4; kk++) {
        wmma::fragment<wmma::matrix_a, 16, 16, 8, wmma::precision::tf32, wmma::row_major> af[4];
        wmma::fragment<wmma::matrix_b, 16, 16, 8, wmma::precision::tf32, wmma::row_major> bf[2];
#pragma unroll
        for (int i = 0; i < 4; i++)
            wmma::load_matrix_sync(af[i], As + (wm * 64 + i * 16) * kLDAs + kk * 8, kLDAs);
#pragma unroll
        for (int j = 0; j < 2; j++) {
            wmma::load_matrix_sync(bf[j], Bs + (kk * 8) * kLDBs + wn * 32 + j * 16, kLDBs);
#pragma unroll
            for (int u = 0; u < bf[j].num_elements; u++)
                bf[j].x[u] = wmma::__float_to_tf32(bf[j].x[u]);
        }
#pragma unroll
        for (int i = 0; i < 4; i++)
#pragma unroll
            for (int j = 0; j < 2; j++)
                wmma::mma_sync(acc[i][j], af[i], bf[j], acc[i][j]);
    }
}

// ---------------------------------------------------------------------------
// k_base: base[e,b,:] = s @ W1s[e] + b1[e]; e==16 -> gating g1 (relu).
// ---------------------------------------------------------------------------
__global__ __launch_bounds__(256) void k_base(
    const float* __restrict__ s,
    const float* __restrict__ W1, const float* __restrict__ b1,
    const float* __restrict__ Wg1, const float* __restrict__ bg1)
{
    __shared__ float ssm[kB * kEMB];   // 32 KB
    __shared__ float red[128][kB];     // 4 KB
    const int t = threadIdx.x;
    const int e = blockIdx.y;
    const int jl = t & 127;
    const int half = t >> 7;
    const int j = blockIdx.x * 128 + jl;

    for (int i = t; i < kB * kEMB; i += 256) ssm[i] = s[i];
    __syncthreads();

    const float* __restrict__ W = (e < kNE) ? (W1 + (size_t)e * kW1R * kH1) : Wg1;

    float acc[kB];
#pragma unroll
    for (int b = 0; b < kB; b++) acc[b] = 0.f;

    const int i0 = half * 512;
#pragma unroll 4
    for (int i = i0; i < i0 + 512; i++) {
        const float w = W[(size_t)i * kH1 + j];
#pragma unroll
        for (int b = 0; b < kB; b++) acc[b] += ssm[b * kEMB + i] * w;
    }

    if (half) {
#pragma unroll
        for (int b = 0; b < kB; b++) red[jl][b] = acc[b];
    }
    __syncthreads();
    if (!half) {
#pragma unroll
        for (int b = 0; b < kB; b++) acc[b] += red[jl][b];
        if (e < kNE) {
            const float bias = b1[e * kH1 + j];
#pragma unroll
            for (int b = 0; b < kB; b++)
                g_base[((size_t)e * kB + b) * kH1 + j] = acc[b] + bias;
        } else {
            const float bias = bg1[j];
#pragma unroll
            for (int b = 0; b < kB; b++)
                g_g1[b * kH1 + j] = fmaxf(acc[b] + bias, 0.f);
        }
    }
}

// ---------------------------------------------------------------------------
// k_gate: 1024 threads; split-K over 8 chunks, smem reduce, then softmax.
// ---------------------------------------------------------------------------
__global__ __launch_bounds__(1024) void k_gate(
    const float* __restrict__ Wg2, const float* __restrict__ bg2)
{
    __shared__ float red[1024];
    const int t = threadIdx.x;
    const int b = t >> 7;
    const int rem = t & 127;
    const int kc = rem >> 4;
    const int x = rem & 15;

    float acc = 0.f;
    const int j0 = kc * 256;
#pragma unroll 4
    for (int j = j0; j < j0 + 256; j++)
        acc += g_g1[b * kH1 + j] * Wg2[j * kNE + x];
    red[t] = acc;
    __syncthreads();

    if (t < 128) {
        const int bb = t >> 4;
        const int xx = t & 15;
        float a = bg2[xx];
#pragma unroll
        for (int k = 0; k < 8; k++) a += red[bb * 128 + k * 16 + xx];

        float mx = a;
#pragma unroll
        for (int o = 8; o >= 1; o >>= 1)
            mx = fmaxf(mx, __shfl_xor_sync(0xffffffffu, mx, o, 16));
        const float ev = expf(a - mx);
        float sm = ev;
#pragma unroll
        for (int o = 8; o >= 1; o >>= 1)
            sm += __shfl_xor_sync(0xffffffffu, sm, o, 16);

        g_w[bb * kNE + xx] = ev / sm;
    }
}

// ---------------------------------------------------------------------------
// k_h: h = tf32( w[b,e] * relu(base + W1c) ). Weight fold + RNA pre-round.
// ---------------------------------------------------------------------------
__global__ __launch_bounds__(256) void k_h(const float* __restrict__ W1)
{
    const unsigned idx = blockIdx.x * 256u + threadIdx.x;
    const int k4 = idx & 511;
    const int m  = (idx >> 9) & 255;
    const int e  = idx >> 17;
    const int c  = m >> 3;
    const int b  = m & 7;

    const float scale = g_w[b * kNE + e];
    const float4 bs = reinterpret_cast<const float4*>(g_base)[(e * kB + b) * (kH1 / 4) + k4];
    const float4 wc = reinterpret_cast<const float4*>(
        W1 + ((size_t)e * kW1R + kEMB + c) * kH1)[k4];

    float4 r;
    r.x = wmma::__float_to_tf32(scale * fmaxf(bs.x + wc.x, 0.f));
    r.y = wmma::__float_to_tf32(scale * fmaxf(bs.y + wc.y, 0.f));
    r.z = wmma::__float_to_tf32(scale * fmaxf(bs.z + wc.z, 0.f));
    r.w = wmma::__float_to_tf32(scale * fmaxf(bs.w + wc.w, 0.f));
    reinterpret_cast<float4*>(g_h)[idx] = r;
}

// ---------------------------------------------------------------------------
// k_gemm_eo: split-K per-expert GEMM. Block tile 128x128, K-tile 32, cp.async
// double buffer, 8 warps (2m x 4n), warp tile 64x32, 2 CTAs/SM.
// Grid: (4 ntiles, 2 mtiles, 32 = expert*2 + khalf).
// ---------------------------------------------------------------------------
__global__ __launch_bounds__(256, 2) void k_gemm_eo(const float* __restrict__ W2)
{
    extern __shared__ float smem[];
    float* As = smem;                  // 2 * kAbuf
    float* Bs = smem + 2 * kAbuf;      // 2 * kBbuf

    const int zz = blockIdx.z;
    const int e  = zz >> 1;
    const int kh = zz & 1;
    const int m0 = blockIdx.y * 128;
    const int n0 = blockIdx.x * 128;
    const int t  = threadIdx.x;
    const int warp = t >> 5;
    const int wm = warp >> 2;
    const int wn = warp & 3;

    const float* A = g_h + (size_t)e * kM * kH1 + (size_t)m0 * kH1 + kh * 1024;
    const float* B = W2 + (size_t)e * kH1 * kH2 + (size_t)(kh * 1024) * kH2 + n0;

    wmma::fragment<wmma::accumulator, 16, 16, 8, float> acc[4][2];
#pragma unroll
    for (int i = 0; i < 4; i++)
#pragma unroll
        for (int j = 0; j < 2; j++) wmma::fill_fragment(acc[i][j], 0.f);

    constexpr int NT = 1024 / 32;
    load_tiles<kH1, kH2>(As, Bs, A, B, 0, t);
    cp_commit();

    for (int it = 0; it < NT; it++) {
        if (it + 1 < NT) {
            load_tiles<kH1, kH2>(As + ((it + 1) & 1) * kAbuf, Bs + ((it + 1) & 1) * kBbuf,
                                 A, B, (it + 1) * 32, t);
            cp_commit();
            cp_wait<1>();
        } else {
            cp_wait<0>();
        }
        __syncthreads();
        gemm_tile_compute(As + (it & 1) * kAbuf, Bs + (it & 1) * kBbuf, wm, wn, acc);
        __syncthreads();
    }

    float* O = g_eo2 + (size_t)zz * kM * kH2 + (size_t)m0 * kH2 + n0;
#pragma unroll
    for (int i = 0; i < 4; i++)
#pragma unroll
        for (int j = 0; j < 2; j++)
            wmma::store_matrix_sync(O + (size_t)(wm * 64 + i * 16) * kH2 + wn * 32 + j * 16,
                                    acc[i][j], kH2, wmma::mem_row_major);
}

// ---------------------------------------------------------------------------
// k_z: z = tf32( sum over 32 partial slabs + sum_e w[b,e]*b2[e] ).
// ---------------------------------------------------------------------------
__global__ __launch_bounds__(256) void k_z(const float* __restrict__ b2)
{
    const int idx = blockIdx.x * 256 + threadIdx.x;
    const int n = idx & (kH2 - 1);
    const int m = idx >> 9;
    const int b = m & 7;

    float acc = 0.f;
#pragma unroll
    for (int p = 0; p < 2 * kNE; p++)
        acc += g_eo2[(size_t)p * (kM * kH2) + idx];
#pragma unroll
    for (int e = 0; e < kNE; e++)
        acc += g_w[b * kNE + e] * b2[e * kH2 + n];
    g_z[idx] = wmma::__float_to_tf32(acc);
}

// ---------------------------------------------------------------------------
// k_gemm_out: (256x512)@(512x16384)+bias, twice. Same pipeline, K=512,
// 2 CTAs/SM. Epilogue stages into the (dead) load buffers. Grid (128, 2, 2).
// ---------------------------------------------------------------------------
__global__ __launch_bounds__(256, 2) void k_gemm_out(
    const float* __restrict__ WA, const float* __restrict__ bA,
    const float* __restrict__ WB, const float* __restrict__ bB,
    float* __restrict__ out)
{
    extern __shared__ float smem[];
    float* As = smem;
    float* Bs = smem + 2 * kAbuf;

    const int mat = blockIdx.z;
    const float* __restrict__ Bw   = (mat ? WB : WA);
    const float* __restrict__ bias = mat ? bB : bA;
    float* __restrict__ o = out + (size_t)mat * kM * kFO;

    const int m0 = blockIdx.y * 128;
    const int n0 = blockIdx.x * 128;
    const int t  = threadIdx.x;
    const int warp = t >> 5;
    const int wm = warp >> 2;
    const int wn = warp & 3;

    const float* A = g_z + (size_t)m0 * kH2;
    const float* B = Bw + n0;

    wmma::fragment<wmma::accumulator, 16, 16, 8, float> acc[4][2];
#pragma unroll
    for (int i = 0; i < 4; i++)
#pragma unroll
        for (int j = 0; j < 2; j++) wmma::fill_fragment(acc[i][j], 0.f);

    constexpr int NT = kH2 / 32;   // 16
    load_tiles<kH2, kFO>(As, Bs, A, B, 0, t);
    cp_commit();

    for (int it = 0; it < NT; it++) {
        if (it + 1 < NT) {
            load_tiles<kH2, kFO>(As + ((it + 1) & 1) * kAbuf, Bs + ((it + 1) & 1) * kBbuf,
                                 A, B, (it + 1) * 32, t);
            cp_commit();
            cp_wait<1>();
        } else {
            cp_wait<0>();
        }
        __syncthreads();
        gemm_tile_compute(As + (it & 1) * kAbuf, Bs + (it & 1) * kBbuf, wm, wn, acc);
        __syncthreads();
    }

    // Epilogue: stage 128x128 tile (stride 132) in dead load buffers.
    __syncthreads();
    float* stage = smem;   // 128*132 = 16896 floats <= 17664 available
#pragma unroll
    for (int i = 0; i < 4; i++)
#pragma unroll
        for (int j = 0; j < 2; j++)
            wmma::store_matrix_sync(stage + (wm * 64 + i * 16) * kLDBs + wn * 32 + j * 16,
                                    acc[i][j], kLDBs, wmma::mem_row_major);
    __syncthreads();

#pragma unroll
    for (int i = 0; i < 16; i++) {
        const int c = t + i * 256;           // float4 chunk in 128x128
        const int row = c >> 5, c4 = c & 31;
        float4 v  = *reinterpret_cast<const float4*>(stage + row * kLDBs + c4 * 4);
        float4 bv = *reinterpret_cast<const float4*>(bias + n0 + c4 * 4);
        v.x += bv.x; v.y += bv.y; v.z += bv.z; v.w += bv.w;
        *reinterpret_cast<float4*>(&o[(size_t)(m0 + row) * kFO + n0 + c4 * 4]) = v;
    }
}

// ---------------------------------------------------------------------------
// kernel_launch
// ---------------------------------------------------------------------------
extern "C" void kernel_launch(void* const* d_in, const int* in_sizes, int n_in,
                              void* d_out, int out_size)
{
    const float* s   = (const float*)d_in[0];
    const float* Wg1 = (const float*)d_in[1];
    const float* bg1 = (const float*)d_in[2];
    const float* Wg2 = (const float*)d_in[3];
    const float* bg2 = (const float*)d_in[4];
    const float* W1  = (const float*)d_in[5];
    const float* b1  = (const float*)d_in[6];
    const float* W2  = (const float*)d_in[7];
    const float* b2  = (const float*)d_in[8];
    const float* WA  = (const float*)d_in[9];
    const float* bA  = (const float*)d_in[10];
    const float* WB  = (const float*)d_in[11];
    const float* bB  = (const float*)d_in[12];
    float* out = (float*)d_out;

    cudaFuncSetAttribute(k_gemm_eo,  cudaFuncAttributeMaxDynamicSharedMemorySize, kSmemGemm);
    cudaFuncSetAttribute(k_gemm_out, cudaFuncAttributeMaxDynamicSharedMemorySize, kSmemGemm);

    k_base<<<dim3(kH1 / 128, kNE + 1), 256>>>(s, W1, b1, Wg1, bg1);
    k_gate<<<1, 1024>>>(Wg2, bg2);
    k_h<<<(kNE * kM * kH1 / 4) / 256, 256>>>(W1);
    k_gemm_eo<<<dim3(kH2 / 128, kM / 128, 2 * kNE), 256, kSmemGemm>>>(W2);
    k_z<<<(kM * kH2) / 256, 256>>>(b2);
    k_gemm_out<<<dim3(kFO / 128, kM / 128, 2), 256, kSmemGemm>>>(WA, bA, WB, bB, out);
}

// round 6
// speedup vs baseline: 1.8640x; 1.0436x over previous
#include <cuda_runtime.h>
#include <cstdint>
#include <mma.h>

using namespace nvcuda;

// ---------------------------------------------------------------------------
// MoE HyperModel, round 5: LDS-bound fix.
// GEMMs: block tile 128x256, warp tile 64x64 (8 warps), 3-stage cp.async
// pipeline with a single __syncthreads per K-tile.
// ---------------------------------------------------------------------------

namespace {
constexpr int kEMB = 1024;
constexpr int kCTX = 32;
constexpr int kNE  = 16;
constexpr int kH1  = 2048;
constexpr int kH2  = 512;
constexpr int kB   = 8;
constexpr int kM   = kCTX * kB;     // 256
constexpr int kFO  = 16384;
constexpr int kW1R = kEMB + kCTX;   // 1056

constexpr int kLDAs = 36;    // smem A tile stride (floats), 128 rows x 32 k
constexpr int kLDBs = 260;   // smem B tile stride (floats), 32 rows x 256 n
constexpr int kAbuf = 128 * kLDAs;   // 4608 floats
constexpr int kBbuf = 32 * kLDBs;    // 8320 floats
constexpr int kStage = kAbuf + kBbuf;               // 12928 floats
constexpr int kSmemGemm = 3 * kStage * 4;           // 155136 bytes
}

// Scratch (static device arrays -- allocation-free).
__device__ float g_g1[kB * kH1];
__device__ float g_w[kB * kNE];
__device__ float g_base[kNE * kB * kH1];
__device__ float g_h[(size_t)kNE * kM * kH1];            // 32 MB, tf32-rounded
__device__ float g_eo2[(size_t)2 * kNE * kM * kH2];      // 16 MB (split-K partials)
__device__ float g_z[kM * kH2];                          // tf32-rounded

// --------------------------- cp.async helpers ------------------------------
__device__ __forceinline__ void cp_async16(float* smem_dst, const float* gmem_src) {
    unsigned int s = (unsigned int)__cvta_generic_to_shared(smem_dst);
    asm volatile("cp.async.cg.shared.global [%0], [%1], 16;\n" :: "r"(s), "l"(gmem_src));
}
__device__ __forceinline__ void cp_commit() {
    asm volatile("cp.async.commit_group;\n");
}
template <int N>
__device__ __forceinline__ void cp_wait() {
    asm volatile("cp.async.wait_group %0;\n" :: "n"(N));
}

// Load one 128x32 A tile + 32x256 B tile into a pipeline stage.
// 256 threads: A = 1024 float4 (4/thread), B = 2048 float4 (8/thread).
template <int LDA_G, int LDB_G>
__device__ __forceinline__ void load_tiles(float* stage,
                                           const float* A, const float* B,
                                           int kt, int t)
{
    float* As = stage;
    float* Bs = stage + kAbuf;
#pragma unroll
    for (int i = 0; i < 4; i++) {
        const int c = t + i * 256;
        const int row = c >> 3, c4 = c & 7;
        cp_async16(As + row * kLDAs + c4 * 4, A + (size_t)row * LDA_G + kt + c4 * 4);
    }
#pragma unroll
    for (int i = 0; i < 8; i++) {
        const int c = t + i * 256;
        const int row = c >> 6, c4 = c & 63;
        cp_async16(Bs + row * kLDBs + c4 * 4, B + (size_t)(kt + row) * LDB_G + c4 * 4);
    }
}

// Warp-tile (64x64) compute over one 32-K stage. B fragments RNA-rounded.
__device__ __forceinline__ void tile_compute(
    const float* stage, int wm, int wn,
    wmma::fragment<wmma::accumulator, 16, 16, 8, float> (&acc)[4][4])
{
    const float* As = stage;
    const float* Bs = stage + kAbuf;
#pragma unroll
    for (int kk = 0; kk < 4; kk++) {
        wmma::fragment<wmma::matrix_b, 16, 16, 8, wmma::precision::tf32, wmma::row_major> bf[4];
#pragma unroll
        for (int j = 0; j < 4; j++) {
            wmma::load_matrix_sync(bf[j], Bs + (kk * 8) * kLDBs + wn * 64 + j * 16, kLDBs);
#pragma unroll
            for (int u = 0; u < bf[j].num_elements; u++)
                bf[j].x[u] = wmma::__float_to_tf32(bf[j].x[u]);
        }
#pragma unroll
        for (int i = 0; i < 4; i++) {
            wmma::fragment<wmma::matrix_a, 16, 16, 8, wmma::precision::tf32, wmma::row_major> af;
            wmma::load_matrix_sync(af, As + (wm * 64 + i * 16) * kLDAs + kk * 8, kLDAs);
#pragma unroll
            for (int j = 0; j < 4; j++)
                wmma::mma_sync(acc[i][j], af, bf[j], acc[i][j]);
        }
    }
}

// ---------------------------------------------------------------------------
// k_base: base[e,b,:] = s @ W1s[e] + b1[e]; e==16 -> gating g1 (relu).
// ---------------------------------------------------------------------------
__global__ __launch_bounds__(256) void k_base(
    const float* __restrict__ s,
    const float* __restrict__ W1, const float* __restrict__ b1,
    const float* __restrict__ Wg1, const float* __restrict__ bg1)
{
    __shared__ float ssm[kB * kEMB];   // 32 KB
    __shared__ float red[128][kB];     // 4 KB
    const int t = threadIdx.x;
    const int e = blockIdx.y;
    const int jl = t & 127;
    const int half = t >> 7;
    const int j = blockIdx.x * 128 + jl;

    for (int i = t; i < kB * kEMB; i += 256) ssm[i] = s[i];
    __syncthreads();

    const float* __restrict__ W = (e < kNE) ? (W1 + (size_t)e * kW1R * kH1) : Wg1;

    float acc[kB];
#pragma unroll
    for (int b = 0; b < kB; b++) acc[b] = 0.f;

    const int i0 = half * 512;
#pragma unroll 4
    for (int i = i0; i < i0 + 512; i++) {
        const float w = W[(size_t)i * kH1 + j];
#pragma unroll
        for (int b = 0; b < kB; b++) acc[b] += ssm[b * kEMB + i] * w;
    }

    if (half) {
#pragma unroll
        for (int b = 0; b < kB; b++) red[jl][b] = acc[b];
    }
    __syncthreads();
    if (!half) {
#pragma unroll
        for (int b = 0; b < kB; b++) acc[b] += red[jl][b];
        if (e < kNE) {
            const float bias = b1[e * kH1 + j];
#pragma unroll
            for (int b = 0; b < kB; b++)
                g_base[((size_t)e * kB + b) * kH1 + j] = acc[b] + bias;
        } else {
            const float bias = bg1[j];
#pragma unroll
            for (int b = 0; b < kB; b++)
                g_g1[b * kH1 + j] = fmaxf(acc[b] + bias, 0.f);
        }
    }
}

// ---------------------------------------------------------------------------
// k_gate: 1024 threads; split-K over 8 chunks, smem reduce, then softmax.
// ---------------------------------------------------------------------------
__global__ __launch_bounds__(1024) void k_gate(
    const float* __restrict__ Wg2, const float* __restrict__ bg2)
{
    __shared__ float red[1024];
    const int t = threadIdx.x;
    const int b = t >> 7;
    const int rem = t & 127;
    const int kc = rem >> 4;
    const int x = rem & 15;

    float acc = 0.f;
    const int j0 = kc * 256;
#pragma unroll 4
    for (int j = j0; j < j0 + 256; j++)
        acc += g_g1[b * kH1 + j] * Wg2[j * kNE + x];
    red[t] = acc;
    __syncthreads();

    if (t < 128) {
        const int bb = t >> 4;
        const int xx = t & 15;
        float a = bg2[xx];
#pragma unroll
        for (int k = 0; k < 8; k++) a += red[bb * 128 + k * 16 + xx];

        float mx = a;
#pragma unroll
        for (int o = 8; o >= 1; o >>= 1)
            mx = fmaxf(mx, __shfl_xor_sync(0xffffffffu, mx, o, 16));
        const float ev = expf(a - mx);
        float sm = ev;
#pragma unroll
        for (int o = 8; o >= 1; o >>= 1)
            sm += __shfl_xor_sync(0xffffffffu, sm, o, 16);

        g_w[bb * kNE + xx] = ev / sm;
    }
}

// ---------------------------------------------------------------------------
// k_h: h = tf32( w[b,e] * relu(base + W1c) ). Weight fold + RNA pre-round.
// ---------------------------------------------------------------------------
__global__ __launch_bounds__(256) void k_h(const float* __restrict__ W1)
{
    const unsigned idx = blockIdx.x * 256u + threadIdx.x;
    const int k4 = idx & 511;
    const int m  = (idx >> 9) & 255;
    const int e  = idx >> 17;
    const int c  = m >> 3;
    const int b  = m & 7;

    const float scale = g_w[b * kNE + e];
    const float4 bs = reinterpret_cast<const float4*>(g_base)[(e * kB + b) * (kH1 / 4) + k4];
    const float4 wc = reinterpret_cast<const float4*>(
        W1 + ((size_t)e * kW1R + kEMB + c) * kH1)[k4];

    float4 r;
    r.x = wmma::__float_to_tf32(scale * fmaxf(bs.x + wc.x, 0.f));
    r.y = wmma::__float_to_tf32(scale * fmaxf(bs.y + wc.y, 0.f));
    r.z = wmma::__float_to_tf32(scale * fmaxf(bs.z + wc.z, 0.f));
    r.w = wmma::__float_to_tf32(scale * fmaxf(bs.w + wc.w, 0.f));
    reinterpret_cast<float4*>(g_h)[idx] = r;
}

// ---------------------------------------------------------------------------
// k_gemm_eo: split-K per-expert GEMM. Block tile 128x256, warp tile 64x64,
// 3-stage single-sync pipeline. Grid: (2 ntiles, 2 mtiles, 32 = e*2 + kh).
// ---------------------------------------------------------------------------
__global__ __launch_bounds__(256) void k_gemm_eo(const float* __restrict__ W2)
{
    extern __shared__ float smem[];

    const int zz = blockIdx.z;
    const int e  = zz >> 1;
    const int kh = zz & 1;
    const int m0 = blockIdx.y * 128;
    const int n0 = blockIdx.x * 256;
    const int t  = threadIdx.x;
    const int warp = t >> 5;
    const int wm = warp >> 2;     // 0..1
    const int wn = warp & 3;      // 0..3

    const float* A = g_h + (size_t)e * kM * kH1 + (size_t)m0 * kH1 + kh * 1024;
    const float* B = W2 + (size_t)e * kH1 * kH2 + (size_t)(kh * 1024) * kH2 + n0;

    wmma::fragment<wmma::accumulator, 16, 16, 8, float> acc[4][4];
#pragma unroll
    for (int i = 0; i < 4; i++)
#pragma unroll
        for (int j = 0; j < 4; j++) wmma::fill_fragment(acc[i][j], 0.f);

    constexpr int NT = 1024 / 32;   // 32
    load_tiles<kH1, kH2>(smem, A, B, 0, t);
    cp_commit();
    load_tiles<kH1, kH2>(smem + kStage, A, B, 32, t);
    cp_commit();

    for (int it = 0; it < NT; it++) {
        if (it + 1 < NT) cp_wait<1>(); else cp_wait<0>();
        __syncthreads();
        if (it + 2 < NT) {
            load_tiles<kH1, kH2>(smem + ((it + 2) % 3) * kStage, A, B, (it + 2) * 32, t);
            cp_commit();
        }
        tile_compute(smem + (it % 3) * kStage, wm, wn, acc);
    }

    float* O = g_eo2 + (size_t)zz * kM * kH2 + (size_t)m0 * kH2 + n0;
#pragma unroll
    for (int i = 0; i < 4; i++)
#pragma unroll
        for (int j = 0; j < 4; j++)
            wmma::store_matrix_sync(O + (size_t)(wm * 64 + i * 16) * kH2 + wn * 64 + j * 16,
                                    acc[i][j], kH2, wmma::mem_row_major);
}

// ---------------------------------------------------------------------------
// k_z: z = tf32( sum over 32 partial slabs + sum_e w[b,e]*b2[e] ).
// ---------------------------------------------------------------------------
__global__ __launch_bounds__(256) void k_z(const float* __restrict__ b2)
{
    const int idx = blockIdx.x * 256 + threadIdx.x;
    const int n = idx & (kH2 - 1);
    const int m = idx >> 9;
    const int b = m & 7;

    float acc = 0.f;
#pragma unroll
    for (int p = 0; p < 2 * kNE; p++)
        acc += g_eo2[(size_t)p * (kM * kH2) + idx];
#pragma unroll
    for (int e = 0; e < kNE; e++)
        acc += g_w[b * kNE + e] * b2[e * kH2 + n];
    g_z[idx] = wmma::__float_to_tf32(acc);
}

// ---------------------------------------------------------------------------
// k_gemm_out: (256x512)@(512x16384)+bias, twice. Block tile 128x256,
// warp 64x64, single-sync pipeline. Grid (64 ntiles, 2 mtiles, 2 mats).
// ---------------------------------------------------------------------------
__global__ __launch_bounds__(256) void k_gemm_out(
    const float* __restrict__ WA, const float* __restrict__ bA,
    const float* __restrict__ WB, const float* __restrict__ bB,
    float* __restrict__ out)
{
    extern __shared__ float smem[];

    const int mat = blockIdx.z;
    const float* __restrict__ Bw   = (mat ? WB : WA);
    const float* __restrict__ bias = mat ? bB : bA;
    float* __restrict__ o = out + (size_t)mat * kM * kFO;

    const int m0 = blockIdx.y * 128;
    const int n0 = blockIdx.x * 256;
    const int t  = threadIdx.x;
    const int warp = t >> 5;
    const int wm = warp >> 2;
    const int wn = warp & 3;

    const float* A = g_z + (size_t)m0 * kH2;
    const float* B = Bw + n0;

    wmma::fragment<wmma::accumulator, 16, 16, 8, float> acc[4][4];
#pragma unroll
    for (int i = 0; i < 4; i++)
#pragma unroll
        for (int j = 0; j < 4; j++) wmma::fill_fragment(acc[i][j], 0.f);

    constexpr int NT = kH2 / 32;   // 16
    load_tiles<kH2, kFO>(smem, A, B, 0, t);
    cp_commit();
    load_tiles<kH2, kFO>(smem + kStage, A, B, 32, t);
    cp_commit();

    for (int it = 0; it < NT; it++) {
        if (it + 1 < NT) cp_wait<1>(); else cp_wait<0>();
        __syncthreads();
        if (it + 2 < NT) {
            load_tiles<kH2, kFO>(smem + ((it + 2) % 3) * kStage, A, B, (it + 2) * 32, t);
            cp_commit();
        }
        tile_compute(smem + (it % 3) * kStage, wm, wn, acc);
    }

    // Epilogue: stage 128x256 tile (stride 260) in smem, add bias, STG.128.
    __syncthreads();
#pragma unroll
    for (int i = 0; i < 4; i++)
#pragma unroll
        for (int j = 0; j < 4; j++)
            wmma::store_matrix_sync(smem + (wm * 64 + i * 16) * kLDBs + wn * 64 + j * 16,
                                    acc[i][j], kLDBs, wmma::mem_row_major);
    __syncthreads();

#pragma unroll
    for (int i = 0; i < 32; i++) {
        const int c = t + i * 256;           // float4 chunk in 128x256
        const int row = c >> 6, c4 = c & 63;
        float4 v  = *reinterpret_cast<const float4*>(smem + row * kLDBs + c4 * 4);
        float4 bv = *reinterpret_cast<const float4*>(bias + n0 + c4 * 4);
        v.x += bv.x; v.y += bv.y; v.z += bv.z; v.w += bv.w;
        *reinterpret_cast<float4*>(&o[(size_t)(m0 + row) * kFO + n0 + c4 * 4]) = v;
    }
}

// ---------------------------------------------------------------------------
// kernel_launch
// ---------------------------------------------------------------------------
extern "C" void kernel_launch(void* const* d_in, const int* in_sizes, int n_in,
                              void* d_out, int out_size)
{
    const float* s   = (const float*)d_in[0];
    const float* Wg1 = (const float*)d_in[1];
    const float* bg1 = (const float*)d_in[2];
    const float* Wg2 = (const float*)d_in[3];
    const float* bg2 = (const float*)d_in[4];
    const float* W1  = (const float*)d_in[5];
    const float* b1  = (const float*)d_in[6];
    const float* W2  = (const float*)d_in[7];
    const float* b2  = (const float*)d_in[8];
    const float* WA  = (const float*)d_in[9];
    const float* bA  = (const float*)d_in[10];
    const float* WB  = (const float*)d_in[11];
    const float* bB  = (const float*)d_in[12];
    float* out = (float*)d_out;

    cudaFuncSetAttribute(k_gemm_eo,  cudaFuncAttributeMaxDynamicSharedMemorySize, kSmemGemm);
    cudaFuncSetAttribute(k_gemm_out, cudaFuncAttributeMaxDynamicSharedMemorySize, kSmemGemm);

    k_base<<<dim3(kH1 / 128, kNE + 1), 256>>>(s, W1, b1, Wg1, bg1);
    k_gate<<<1, 1024>>>(Wg2, bg2);
    k_h<<<(kNE * kM * kH1 / 4) / 256, 256>>>(W1);
    k_gemm_eo<<<dim3(kH2 / 256, kM / 128, 2 * kNE), 256, kSmemGemm>>>(W2);
    k_z<<<(kM * kH2) / 256, 256>>>(b2);
    k_gemm_out<<<dim3(kFO / 256, kM / 128, 2), 256, kSmemGemm>>>(WA, bA, WB, bB, out);
}